// round 15
// baseline (speedup 1.0000x reference)
#include <cuda_runtime.h>
#include <cuda_fp16.h>
#include <math.h>
#include <stdint.h>

#define BATCH 16
#define N1D 1024
#define CCH 256

// ---------------- device scratch ----------------
__device__ float g_p1[BATCH * N1D * CCH];
__device__ float g_x3[BATCH * 64 * CCH];
__device__ float g_att2[BATCH * 256 * 256];
__device__ float g_att3[BATCH * 64 * 64];
__device__ __half g_x1[BATCH * N1D * CCH];
__device__ __half g_x2[BATCH * 256 * CCH];
__device__ __half g_f1[BATCH * N1D * CCH];
__device__ __half g_f2[BATCH * 256 * 512];
__device__ __half g_f3[BATCH * 64 * 1024];
__device__ __half g_w1[256 * 256];
__device__ __half g_w2[512 * 256];
__device__ __half g_w3[1024 * 256];

// ---------------- warp-MMA helpers ----------------
__device__ __forceinline__ uint32_t smem_u32(const void* p) {
    uint32_t a;
    asm("{ .reg .u64 t; cvta.to.shared.u64 t, %1; cvt.u32.u64 %0, t; }"
        : "=r"(a) : "l"(p));
    return a;
}
__device__ __forceinline__ void ldsm4(uint32_t* r, uint32_t a) {
    asm volatile("ldmatrix.sync.aligned.m8n8.x4.shared.b16 {%0,%1,%2,%3}, [%4];"
        : "=r"(r[0]), "=r"(r[1]), "=r"(r[2]), "=r"(r[3]) : "r"(a));
}
__device__ __forceinline__ void ldsm4t(uint32_t* r, uint32_t a) {
    asm volatile("ldmatrix.sync.aligned.m8n8.x4.trans.shared.b16 {%0,%1,%2,%3}, [%4];"
        : "=r"(r[0]), "=r"(r[1]), "=r"(r[2]), "=r"(r[3]) : "r"(a));
}
__device__ __forceinline__ void mma_f16(float* d, const uint32_t* a,
                                        const uint32_t* b) {
    asm volatile(
        "mma.sync.aligned.m16n8k16.row.col.f32.f16.f16.f32 "
        "{%0,%1,%2,%3}, {%4,%5,%6,%7}, {%8,%9}, {%0,%1,%2,%3};"
        : "+f"(d[0]), "+f"(d[1]), "+f"(d[2]), "+f"(d[3])
        : "r"(a[0]), "r"(a[1]), "r"(a[2]), "r"(a[3]), "r"(b[0]), "r"(b[1]));
}
__device__ __forceinline__ unsigned pack_h(__half a, __half b) {
    return ((unsigned)__half_as_ushort(b) << 16) | (unsigned)__half_as_ushort(a);
}

// ---------------------------------------------------------------------------
// cvt + bias-init in ONE launch.
// ---------------------------------------------------------------------------
__global__ void cvt_all_kernel(
    const float* __restrict__ f1, const float* __restrict__ f2,
    const float* __restrict__ f3, const float* __restrict__ w1,
    const float* __restrict__ w2, const float* __restrict__ w3,
    const float* __restrict__ b3,
    __half* __restrict__ o1, __half* __restrict__ o2, __half* __restrict__ o3,
    __half* __restrict__ o4, __half* __restrict__ o5, __half* __restrict__ o6,
    float* __restrict__ x3)
{
    int bi = blockIdx.x;
    if (bi >= 7616) {
        int idx = (bi - 7616) * 256 + threadIdx.x;
        int cj = idx & 63;
        float4 bv = *(const float4*)&b3[cj * 4];
        *(float4*)&x3[idx * 4] = bv;
        return;
    }
    const float* src; __half* dst; int base;
    if      (bi < 4096) { src = f1; dst = o1; base = 0; }
    else if (bi < 6144) { src = f2; dst = o2; base = 4096; }
    else if (bi < 7168) { src = f3; dst = o3; base = 6144; }
    else if (bi < 7232) { src = w1; dst = o4; base = 7168; }
    else if (bi < 7360) { src = w2; dst = o5; base = 7232; }
    else                { src = w3; dst = o6; base = 7360; }
    size_t i4 = (size_t)(bi - base) * 256 + threadIdx.x;
    float4 v = *(const float4*)(src + i4 * 4);
    uint2 o;
    o.x = pack_h(__float2half_rn(v.x), __float2half_rn(v.y));
    o.y = pack_h(__float2half_rn(v.z), __float2half_rn(v.w));
    *(uint2*)(dst + i4 * 4) = o;
}

// ---------------------------------------------------------------------------
// ALL projections in ONE launch (fp16 inputs), DOUBLE-BUFFERED staging.
// blocks: proj3 0..63 (ksplit, atomic) | proj2 64..127 | proj1 128..383
// ---------------------------------------------------------------------------
#define PAST 72
#define PWST 264
#define PBUF (64 * PAST + 64 * PWST)   // halfs per buffer

__global__ __launch_bounds__(256) void projall_kernel(
    const __half* __restrict__ hf1, const __half* __restrict__ hw1,
    const float* __restrict__ b1, float* __restrict__ p1, __half* __restrict__ x1,
    const __half* __restrict__ hf2, const __half* __restrict__ hw2,
    const float* __restrict__ b2, __half* __restrict__ x2,
    const __half* __restrict__ hf3, const __half* __restrict__ hw3,
    float* __restrict__ x3)
{
    extern __shared__ char smbuf[];
    __half* base0 = (__half*)smbuf;

    const int bi = blockIdx.x;
    const __half *A, *W; const float* bias = nullptr;
    int KDIM, kbase = 0, kd, row0;
    float* outF = nullptr; __half* outH = nullptr; int atomicF = 0;
    if (bi < 64) {
        int s = bi;
        A = hf3; W = hw3; KDIM = 1024; kd = 256; kbase = (s >> 4) * 256;
        row0 = (s & 15) * 64; outF = x3; atomicF = 1;
    } else if (bi < 128) {
        A = hf2; W = hw2; bias = b2; KDIM = 512; kd = 512;
        row0 = (bi - 64) * 64; outH = x2;
    } else {
        A = hf1; W = hw1; bias = b1; KDIM = 256; kd = 256;
        row0 = (bi - 128) * 64; outF = p1; outH = x1;
    }

    const int t = threadIdx.x, w = t >> 5, l = t & 31;
    const int wr = w >> 2, wc = w & 3;
    const int aRow = l & 15, aCol = (l >> 4) * 8;

    float acc[2][8][4];
#pragma unroll
    for (int mf = 0; mf < 2; mf++)
#pragma unroll
        for (int nf = 0; nf < 8; nf++)
#pragma unroll
            for (int e = 0; e < 4; e++) acc[mf][nf][e] = 0.f;

    const int nIter = kd >> 6;

#define PSTAGE(BUF, KG) do {                                                   \
    __half* sA_ = base0 + (BUF) * PBUF;                                        \
    __half* sW_ = sA_ + 64 * PAST;                                             \
    for (int idx = t; idx < 512; idx += 256) {                                 \
        int r_ = idx >> 3, c_ = idx & 7;                                       \
        *(uint4*)(sA_ + r_ * PAST + c_ * 8) =                                  \
            *(const uint4*)(A + (size_t)(row0 + r_) * KDIM + (KG) + c_ * 8);   \
    }                                                                          \
    for (int idx = t; idx < 2048; idx += 256) {                                \
        int r_ = idx >> 5, c_ = idx & 31;                                      \
        *(uint4*)(sW_ + r_ * PWST + c_ * 8) =                                  \
            *(const uint4*)(W + (size_t)((KG) + r_) * 256 + c_ * 8);           \
    }                                                                          \
} while (0)

    PSTAGE(0, kbase);
    __syncthreads();

    for (int it = 0; it < nIter; it++) {
        const int cb = it & 1;
        if (it + 1 < nIter) PSTAGE(cb ^ 1, kbase + (it + 1) * 64);
        const uint32_t sa0 = smem_u32(base0 + cb * PBUF);
        const uint32_t sw0 = sa0 + 64 * PAST * 2;
#pragma unroll
        for (int ks = 0; ks < 4; ks++) {
            uint32_t a[2][4];
#pragma unroll
            for (int mf = 0; mf < 2; mf++) {
                uint32_t off = (uint32_t)((wr * 32 + mf * 16 + aRow) * PAST +
                                          ks * 16 + aCol) * 2;
                ldsm4(a[mf], sa0 + off);
            }
#pragma unroll
            for (int p = 0; p < 4; p++) {
                uint32_t bfr[4];
                uint32_t off = (uint32_t)((ks * 16 + aRow) * PWST +
                                          wc * 64 + p * 16 + aCol) * 2;
                ldsm4t(bfr, sw0 + off);
#pragma unroll
                for (int mf = 0; mf < 2; mf++) {
                    mma_f16(acc[mf][p * 2 + 0], a[mf], &bfr[0]);
                    mma_f16(acc[mf][p * 2 + 1], a[mf], &bfr[2]);
                }
            }
        }
        __syncthreads();
    }

#pragma unroll
    for (int mf = 0; mf < 2; mf++)
#pragma unroll
    for (int nf = 0; nf < 8; nf++)
#pragma unroll
    for (int pr = 0; pr < 2; pr++) {
        int r = row0 + wr * 32 + mf * 16 + (l >> 2) + pr * 8;
        int c = wc * 64 + nf * 8 + (l & 3) * 2;
        float v0 = acc[mf][nf][pr * 2 + 0];
        float v1 = acc[mf][nf][pr * 2 + 1];
        if (atomicF) {
            atomicAdd(outF + (size_t)r * 256 + c,     v0);
            atomicAdd(outF + (size_t)r * 256 + c + 1, v1);
        } else {
            v0 += bias[c]; v1 += bias[c + 1];
            if (outF) *(float2*)(outF + (size_t)r * 256 + c) = make_float2(v0, v1);
            *(uint32_t*)(outH + (size_t)r * 256 + c) =
                pack_h(__float2half_rn(v0), __float2half_rn(v1));
        }
    }
}

// ---------------------------------------------------------------------------
// gram att2 (fp16 MMA, blocks 0..63) + att3 gram (fp32, blocks 64..79)
// ---------------------------------------------------------------------------
__global__ __launch_bounds__(256) void gram_att3_kernel(
    const __half* __restrict__ X2, float* __restrict__ att2,
    const float* __restrict__ X3, float* __restrict__ att3)
{
    constexpr int XST = 72;
    extern __shared__ char smbuf[];

    if (blockIdx.x < 64) {
        __half* sI = (__half*)smbuf;
        __half* sJ = sI + 128 * XST;
        const int idx0 = blockIdx.x;
        const int b = idx0 >> 2;
        const int i0 = ((idx0 >> 1) & 1) * 128, j0 = (idx0 & 1) * 128;
        const int t = threadIdx.x, w = t >> 5, l = t & 31;
        const int wr = w >> 1, wc = w & 1;
        const int aRow = l & 15, aCol = (l >> 4) * 8;
        const int bRow = (l >> 4) * 8 + (l & 7), bCol = ((l >> 3) & 1) * 8;
        const __half* Xb = X2 + (size_t)b * 256 * CCH;

        float acc[2][8][4];
#pragma unroll
        for (int mf = 0; mf < 2; mf++)
#pragma unroll
            for (int nf = 0; nf < 8; nf++)
#pragma unroll
                for (int e = 0; e < 4; e++) acc[mf][nf][e] = 0.f;

        const uint32_t si0 = smem_u32(sI), sj0 = smem_u32(sJ);

        for (int kb = 0; kb < CCH; kb += 64) {
            __syncthreads();
            for (int idx = t; idx < 128 * 8; idx += 256) {
                int r = idx >> 3, c = idx & 7;
                *(uint4*)(sI + r * XST + c * 8) =
                    *(const uint4*)(Xb + (size_t)(i0 + r) * CCH + kb + c * 8);
                *(uint4*)(sJ + r * XST + c * 8) =
                    *(const uint4*)(Xb + (size_t)(j0 + r) * CCH + kb + c * 8);
            }
            __syncthreads();
#pragma unroll
            for (int ks = 0; ks < 4; ks++) {
                uint32_t a[2][4];
#pragma unroll
                for (int mf = 0; mf < 2; mf++) {
                    uint32_t off = (uint32_t)((wr * 32 + mf * 16 + aRow) * XST +
                                              ks * 16 + aCol) * 2;
                    ldsm4(a[mf], si0 + off);
                }
#pragma unroll
                for (int bt = 0; bt < 4; bt++) {
                    uint32_t bfr[4];
                    uint32_t off = (uint32_t)((wc * 64 + bt * 16 + bRow) * XST +
                                              ks * 16 + bCol) * 2;
                    ldsm4(bfr, sj0 + off);
#pragma unroll
                    for (int mf = 0; mf < 2; mf++) {
                        mma_f16(acc[mf][bt * 2 + 0], a[mf], &bfr[0]);
                        mma_f16(acc[mf][bt * 2 + 1], a[mf], &bfr[2]);
                    }
                }
            }
        }

#pragma unroll
        for (int mf = 0; mf < 2; mf++)
#pragma unroll
        for (int nf = 0; nf < 8; nf++)
#pragma unroll
        for (int pr = 0; pr < 2; pr++) {
            int i = i0 + wr * 32 + mf * 16 + (l >> 2) + pr * 8;
            int j = j0 + wc * 64 + nf * 8 + (l & 3) * 2;
            *(float2*)(att2 + (size_t)b * 256 * 256 + (size_t)i * 256 + j) =
                make_float2(acc[mf][nf][pr * 2 + 0], acc[mf][nf][pr * 2 + 1]);
        }
    } else {
        float* Ai = (float*)smbuf;
        const int b = blockIdx.x - 64;
        const int t = threadIdx.x;
        const int ty = t >> 4, tx = t & 15;
        const int r0 = ty * 4, c0 = tx * 4;
        const float* Xb = X3 + (size_t)b * 64 * CCH;

        float acc[4][4] = {};
        for (int k0 = 0; k0 < CCH; k0 += 32) {
            __syncthreads();
#pragma unroll
            for (int i = 0; i < 8; i++) {
                int lin = t + 256 * i;
                int r = lin >> 5, k = lin & 31;
                Ai[k * 65 + r] = Xb[(size_t)r * CCH + k0 + k];
            }
            __syncthreads();
#pragma unroll
            for (int k = 0; k < 32; k++) {
                float a[4], bb[4];
#pragma unroll
                for (int i = 0; i < 4; i++) a[i]  = Ai[k * 65 + r0 + i];
#pragma unroll
                for (int j = 0; j < 4; j++) bb[j] = Ai[k * 65 + c0 + j];
#pragma unroll
                for (int i = 0; i < 4; i++)
#pragma unroll
                    for (int j = 0; j < 4; j++)
                        acc[i][j] += a[i] * bb[j];
            }
        }
#pragma unroll
        for (int i = 0; i < 4; i++) {
            float4 o = make_float4(acc[i][0], acc[i][1], acc[i][2], acc[i][3]);
            *(float4*)&att3[(size_t)b * 64 * 64 + (size_t)(r0 + i) * 64 + c0] = o;
        }
    }
}

// ---------------------------------------------------------------------------
// Fused sigmoid-attention: 128x128 tiles, 512 threads, grid 128.
// K tiles prefetched via registers (LDG overlaps gate+GEMM2).
// Epilogue: raw fp16 S round-trip + row-contiguous gate pass.
// ---------------------------------------------------------------------------
#define KST 264
#define SST 136

__global__ __launch_bounds__(512, 1) void fused_mma_kernel(
    const __half* __restrict__ x1,
    const float* __restrict__ p1,
    const float* __restrict__ att2, const float* __restrict__ att3,
    const float* __restrict__ pa1, const float* __restrict__ pa2,
    const float* __restrict__ pa3, float* __restrict__ out)
{
    extern __shared__ char smbuf[];
    __half* Qs = (__half*)smbuf;            // 128 x 264
    __half* Ks = Qs + 128 * KST;            // 128 x 264
    __half* Ss = Ks + 128 * KST;            // 128 x 136
    float* A2s = (float*)(Ss + 128 * SST);  // 33 x 257 (x a2)
    float* A3s = A2s + 33 * 257;            // 9 x 65  (x a3)

    const int b  = blockIdx.y;
    const int n0 = blockIdx.x * 128;
    const int t  = threadIdx.x, w = t >> 5, l = t & 31;
    const int wn = w & 3, wc = w >> 2;
    const int aRow = l & 15, aCol = (l >> 4) * 8;
    const int bRow = (l >> 4) * 8 + (l & 7);
    const int bCol = ((l >> 3) & 1) * 8;

    const __half* Xb = x1 + (size_t)b * N1D * CCH;
    const float sa1 = *pa1, sa2 = *pa2, sa3 = *pa3;
    const int r2lo = n0 >> 2, r3lo = n0 >> 4;

    // per-thread K staging coordinates (8 uint4 per thread)
    const int pr_r = t >> 2, pr_c = (t & 3) * 8;   // rows t>>2 + 128-step? no:
    // 4096 uint4 = 128 rows x 32 chunks; thread covers (t>>2 + 0) rows? Use:
    // idx = t + 512*i -> r = idx>>5, c = idx&31  (as before)

    uint4 pf[8];
#pragma unroll
    for (int i = 0; i < 8; i++) {
        int idx = t + 512 * i;
        int r = idx >> 5, c = idx & 31;
        pf[i] = *(const uint4*)(Xb + (size_t)r * CCH + c * 8);   // m-tile 0
    }

#pragma unroll
    for (int i = 0; i < 8; i++) {
        int idx = t + 512 * i;
        int r = idx >> 5, c = idx & 31;
        *(uint4*)(Qs + r * KST + c * 8) =
            *(const uint4*)(Xb + (size_t)(n0 + r) * CCH + c * 8);
    }
    for (int i = t; i < 33 * 256; i += 512) {
        int rr = i >> 8, cc = i & 255;
        A2s[rr * 257 + cc] =
            sa2 * att2[((size_t)b * 256 + min(r2lo + rr, 255)) * 256 + cc];
    }
    for (int i = t; i < 9 * 64; i += 512) {
        int rr = i >> 6, cc = i & 63;
        A3s[rr * 65 + cc] =
            sa3 * att3[((size_t)b * 64 + min(r3lo + rr, 63)) * 64 + cc];
    }

    const uint32_t q0 = smem_u32(Qs);
    const uint32_t k0 = smem_u32(Ks);
    const uint32_t s0 = smem_u32(Ss);

    // gate-pass constants
    const int grow = t >> 2, gcq = t & 3;
    const int gn = n0 + grow;
    const int grn = gn >> 2;
    const float gfn = (float)(gn & 3) * 0.25f;
    const float* GR0 = A2s + (grn - r2lo) * 257;
    const float* GR1 = A2s + (min(grn + 1, 255) - r2lo) * 257;
    const int grn3 = gn >> 4;
    const float gfn3 = (float)(gn & 15) * 0.0625f;
    const float* GT0 = A3s + (grn3 - r3lo) * 65;
    const float* GT1 = A3s + (min(grn3 + 1, 63) - r3lo) * 65;
    __half* Srow = Ss + grow * SST + gcq * 32;

    float O[2][8][4];
#pragma unroll
    for (int mf = 0; mf < 2; mf++)
#pragma unroll
        for (int f = 0; f < 8; f++)
#pragma unroll
            for (int e = 0; e < 4; e++) O[mf][f][e] = 0.f;

    for (int mt = 0; mt < 8; mt++) {
        const int m0 = mt * 128;
        __syncthreads();                     // Ks free (GEMM2 mt-1 done)
#pragma unroll
        for (int i = 0; i < 8; i++) {        // STS prefetched K tile
            int idx = t + 512 * i;
            int r = idx >> 5, c = idx & 31;
            *(uint4*)(Ks + r * KST + c * 8) = pf[i];
        }
        __syncthreads();

        // ---- GEMM1: S(128x128) = Q . K^T ----
        float Sa[2][4][4];
#pragma unroll
        for (int mf = 0; mf < 2; mf++)
#pragma unroll
            for (int nf = 0; nf < 4; nf++)
#pragma unroll
                for (int e = 0; e < 4; e++) Sa[mf][nf][e] = 0.f;

#pragma unroll
        for (int kc = 0; kc < 16; kc++) {
            uint32_t a[2][4];
#pragma unroll
            for (int mf = 0; mf < 2; mf++) {
                uint32_t offA = (uint32_t)((wn * 32 + mf * 16 + aRow) * KST +
                                           kc * 16 + aCol) * 2;
                ldsm4(a[mf], q0 + offA);
            }
            uint32_t bf[4][2];
#pragma unroll
            for (int bt = 0; bt < 2; bt++) {
                uint32_t r[4];
                uint32_t offB = (uint32_t)((wc * 32 + bt * 16 + bRow) * KST +
                                           kc * 16 + bCol) * 2;
                ldsm4(r, k0 + offB);
                bf[bt * 2][0] = r[0]; bf[bt * 2][1] = r[1];
                bf[bt * 2 + 1][0] = r[2]; bf[bt * 2 + 1][1] = r[3];
            }
#pragma unroll
            for (int mf = 0; mf < 2; mf++)
#pragma unroll
                for (int nf = 0; nf < 4; nf++)
                    mma_f16(Sa[mf][nf], a[mf], bf[nf]);
        }

        // ---- write raw S (fp16) ----
#pragma unroll
        for (int mf = 0; mf < 2; mf++)
#pragma unroll
        for (int nf = 0; nf < 4; nf++)
#pragma unroll
        for (int pr = 0; pr < 2; pr++) {
            int row_l = wn * 32 + mf * 16 + (l >> 2) + pr * 8;
            int col_l = wc * 32 + nf * 8 + (l & 3) * 2;
            *(uint32_t*)&Ss[row_l * SST + col_l] =
                pack_h(__float2half_rn(Sa[mf][nf][pr * 2 + 0]),
                       __float2half_rn(Sa[mf][nf][pr * 2 + 1]));
        }

        // ---- prefetch next K tile into registers (Sa now dead) ----
        if (mt + 1 < 8) {
            const __half* nK = Xb + (size_t)(m0 + 128) * CCH;
#pragma unroll
            for (int i = 0; i < 8; i++) {
                int idx = t + 512 * i;
                int r = idx >> 5, c = idx & 31;
                pf[i] = *(const uint4*)(nK + (size_t)r * CCH + c * 8);
            }
        }
        __syncthreads();

        // ---- gate pass: row-contiguous, in-place ----
        {
            const int mbase = m0 + gcq * 32;
            float ta = 0.f, td = 0.f;
#pragma unroll
            for (int s = 0; s < 4; s++) {
                const int mb = mbase + s * 8;
                if ((s & 1) == 0) {
                    int c3  = mb >> 4;
                    int c31 = min(c3 + 1, 63);
                    float t0v = GT0[c3]  + gfn3 * (GT1[c3]  - GT0[c3]);
                    float t1v = GT0[c31] + gfn3 * (GT1[c31] - GT0[c31]);
                    ta = t0v;
                    td = (t1v - t0v) * 0.0625f;
                }
                const int cm  = mb >> 2;
                const int cmc = min(cm + 2, 255);
                float la = GR0[cm]     + gfn * (GR1[cm]     - GR0[cm]);
                float lb = GR0[cm + 1] + gfn * (GR1[cm + 1] - GR0[cm + 1]);
                float lc = GR0[cmc]    + gfn * (GR1[cmc]    - GR0[cmc]);
                float d0 = (lb - la) * 0.25f;
                float d1 = (lc - lb) * 0.25f;
                const float c16 = (float)((s & 1) * 8);

                uint4 raw = *(uint4*)(Srow + s * 8);
                uint32_t rw[4] = {raw.x, raw.y, raw.z, raw.w};
                uint32_t ow[4];
#pragma unroll
                for (int pj = 0; pj < 4; pj++) {
                    float2 sv = __half22float2(*(__half2*)&rw[pj]);
                    float res[2];
#pragma unroll
                    for (int e = 0; e < 2; e++) {
                        int j = pj * 2 + e;
                        float base = (j < 4) ? la : lb;
                        float dd   = (j < 4) ? d0 : d1;
                        float v2 = base + (float)(j & 3) * dd;
                        float v3 = ta + (c16 + (float)j) * td;
                        float Sv = (e == 0) ? sv.x : sv.y;
                        float val = fmaf(sa1, Sv, v2 + v3);
                        res[e] = 1.0f / (1.0f + __expf(-val));
                    }
                    ow[pj] = pack_h(__float2half_rn(res[0]),
                                    __float2half_rn(res[1]));
                }
                *(uint4*)(Srow + s * 8) = make_uint4(ow[0], ow[1], ow[2], ow[3]);
            }
        }
        __syncthreads();

        // ---- GEMM2: O(128x256) += S(128x128) . K(128x256) ----
#pragma unroll
        for (int kc = 0; kc < 8; kc++) {
            uint32_t sA[2][4];
#pragma unroll
            for (int mf = 0; mf < 2; mf++) {
                uint32_t offA = (uint32_t)((wn * 32 + mf * 16 + aRow) * SST +
                                           kc * 16 + aCol) * 2;
                ldsm4(sA[mf], s0 + offA);
            }
#pragma unroll
            for (int p = 0; p < 4; p++) {
                uint32_t r[4];
                uint32_t offB = (uint32_t)((kc * 16 + aRow) * KST +
                                           wc * 64 + p * 16 + aCol) * 2;
                ldsm4t(r, k0 + offB);
#pragma unroll
                for (int mf = 0; mf < 2; mf++) {
                    mma_f16(O[mf][p * 2 + 0], sA[mf], &r[0]);
                    mma_f16(O[mf][p * 2 + 1], sA[mf], &r[2]);
                }
            }
        }
    }

    // ---- final: out = O + p1 ----
#pragma unroll
    for (int mf = 0; mf < 2; mf++)
#pragma unroll
    for (int f = 0; f < 8; f++)
#pragma unroll
    for (int pr = 0; pr < 2; pr++) {
        const int n  = n0 + wn * 32 + mf * 16 + (l >> 2) + pr * 8;
        const int ch = wc * 64 + f * 8 + (l & 3) * 2;
        const size_t o = ((size_t)(b * N1D + n)) * CCH + ch;
        float2 pv = *(const float2*)(p1 + o);
        *(float2*)(out + o) = make_float2(O[mf][f][pr * 2 + 0] + pv.x,
                                          O[mf][f][pr * 2 + 1] + pv.y);
    }
}

// ---------------------------------------------------------------------------
extern "C" void kernel_launch(void* const* d_in, const int* in_sizes, int n_in,
                              void* d_out, int out_size)
{
    const float* f1 = (const float*)d_in[0];
    const float* f2 = (const float*)d_in[1];
    const float* f3 = (const float*)d_in[2];
    const float* w1 = (const float*)d_in[3];
    const float* b1 = (const float*)d_in[4];
    const float* w2 = (const float*)d_in[5];
    const float* b2 = (const float*)d_in[6];
    const float* w3 = (const float*)d_in[7];
    const float* b3 = (const float*)d_in[8];
    const float* a1 = (const float*)d_in[9];
    const float* a2 = (const float*)d_in[10];
    const float* a3 = (const float*)d_in[11];
    float* out = (float*)d_out;

    float *p1, *x3, *att2, *att3;
    __half *x1, *x2, *hf1, *hf2, *hf3, *hw1, *hw2, *hw3;
    cudaGetSymbolAddress((void**)&p1,   g_p1);
    cudaGetSymbolAddress((void**)&x3,   g_x3);
    cudaGetSymbolAddress((void**)&att2, g_att2);
    cudaGetSymbolAddress((void**)&att3, g_att3);
    cudaGetSymbolAddress((void**)&x1,   g_x1);
    cudaGetSymbolAddress((void**)&x2,   g_x2);
    cudaGetSymbolAddress((void**)&hf1,  g_f1);
    cudaGetSymbolAddress((void**)&hf2,  g_f2);
    cudaGetSymbolAddress((void**)&hf3,  g_f3);
    cudaGetSymbolAddress((void**)&hw1,  g_w1);
    cudaGetSymbolAddress((void**)&hw2,  g_w2);
    cudaGetSymbolAddress((void**)&hw3,  g_w3);

    cvt_all_kernel<<<7872, 256>>>(f1, f2, f3, w1, w2, w3, b3,
                                  hf1, hf2, hf3, hw1, hw2, hw3, x3);

    const int smemP = PBUF * 2 * 2;   // two buffers, halfs->bytes
    cudaFuncSetAttribute(projall_kernel,
                         cudaFuncAttributeMaxDynamicSharedMemorySize, smemP);
    projall_kernel<<<384, 256, smemP>>>(hf1, hw1, b1, p1, x1,
                                        hf2, hw2, b2, x2,
                                        hf3, hw3, x3);

    const int smemG = 2 * 128 * 72 * 2;
    cudaFuncSetAttribute(gram_att3_kernel,
                         cudaFuncAttributeMaxDynamicSharedMemorySize, smemG);
    gram_att3_kernel<<<80, 256, smemG>>>(x2, att2, x3, att3);

    const int smemF = (128 * KST * 2 + 128 * SST) * 2
                      + (33 * 257 + 9 * 65) * 4;
    cudaFuncSetAttribute(fused_mma_kernel,
                         cudaFuncAttributeMaxDynamicSharedMemorySize, smemF);
    fused_mma_kernel<<<dim3(8, BATCH), 512, smemF>>>(
        x1, p1, att2, att3, a1, a2, a3, out);
}

// round 16
// speedup vs baseline: 1.0469x; 1.0469x over previous
#include <cuda_runtime.h>
#include <cuda_fp16.h>
#include <math.h>
#include <stdint.h>

#define BATCH 16
#define N1D 1024
#define CCH 256

// ---------------- device scratch ----------------
__device__ float g_p1[BATCH * N1D * CCH];
__device__ float g_x3[BATCH * 64 * CCH];
__device__ float g_att2[BATCH * 256 * 256];
__device__ float g_att3[BATCH * 64 * 64];
__device__ __half g_x1[BATCH * N1D * CCH];
__device__ __half g_x2[BATCH * 256 * CCH];
__device__ __half g_f1[BATCH * N1D * CCH];
__device__ __half g_f2[BATCH * 256 * 512];
__device__ __half g_f3[BATCH * 64 * 1024];
__device__ __half g_w1[256 * 256];
__device__ __half g_w2[512 * 256];
__device__ __half g_w3[1024 * 256];

// ---------------- warp-MMA helpers ----------------
__device__ __forceinline__ uint32_t smem_u32(const void* p) {
    uint32_t a;
    asm("{ .reg .u64 t; cvta.to.shared.u64 t, %1; cvt.u32.u64 %0, t; }"
        : "=r"(a) : "l"(p));
    return a;
}
__device__ __forceinline__ void ldsm4(uint32_t* r, uint32_t a) {
    asm volatile("ldmatrix.sync.aligned.m8n8.x4.shared.b16 {%0,%1,%2,%3}, [%4];"
        : "=r"(r[0]), "=r"(r[1]), "=r"(r[2]), "=r"(r[3]) : "r"(a));
}
__device__ __forceinline__ void ldsm4t(uint32_t* r, uint32_t a) {
    asm volatile("ldmatrix.sync.aligned.m8n8.x4.trans.shared.b16 {%0,%1,%2,%3}, [%4];"
        : "=r"(r[0]), "=r"(r[1]), "=r"(r[2]), "=r"(r[3]) : "r"(a));
}
__device__ __forceinline__ void mma_f16(float* d, const uint32_t* a,
                                        const uint32_t* b) {
    asm volatile(
        "mma.sync.aligned.m16n8k16.row.col.f32.f16.f16.f32 "
        "{%0,%1,%2,%3}, {%4,%5,%6,%7}, {%8,%9}, {%0,%1,%2,%3};"
        : "+f"(d[0]), "+f"(d[1]), "+f"(d[2]), "+f"(d[3])
        : "r"(a[0]), "r"(a[1]), "r"(a[2]), "r"(a[3]), "r"(b[0]), "r"(b[1]));
}
__device__ __forceinline__ unsigned pack_h(__half a, __half b) {
    return ((unsigned)__half_as_ushort(b) << 16) | (unsigned)__half_as_ushort(a);
}

// ---------------------------------------------------------------------------
// cvt + bias-init in ONE launch.
// ---------------------------------------------------------------------------
__global__ void cvt_all_kernel(
    const float* __restrict__ f1, const float* __restrict__ f2,
    const float* __restrict__ f3, const float* __restrict__ w1,
    const float* __restrict__ w2, const float* __restrict__ w3,
    const float* __restrict__ b3,
    __half* __restrict__ o1, __half* __restrict__ o2, __half* __restrict__ o3,
    __half* __restrict__ o4, __half* __restrict__ o5, __half* __restrict__ o6,
    float* __restrict__ x3)
{
    int bi = blockIdx.x;
    if (bi >= 7616) {
        int idx = (bi - 7616) * 256 + threadIdx.x;
        int cj = idx & 63;
        float4 bv = *(const float4*)&b3[cj * 4];
        *(float4*)&x3[idx * 4] = bv;
        return;
    }
    const float* src; __half* dst; int base;
    if      (bi < 4096) { src = f1; dst = o1; base = 0; }
    else if (bi < 6144) { src = f2; dst = o2; base = 4096; }
    else if (bi < 7168) { src = f3; dst = o3; base = 6144; }
    else if (bi < 7232) { src = w1; dst = o4; base = 7168; }
    else if (bi < 7360) { src = w2; dst = o5; base = 7232; }
    else                { src = w3; dst = o6; base = 7360; }
    size_t i4 = (size_t)(bi - base) * 256 + threadIdx.x;
    float4 v = *(const float4*)(src + i4 * 4);
    uint2 o;
    o.x = pack_h(__float2half_rn(v.x), __float2half_rn(v.y));
    o.y = pack_h(__float2half_rn(v.z), __float2half_rn(v.w));
    *(uint2*)(dst + i4 * 4) = o;
}

// ---------------------------------------------------------------------------
// ALL projections in ONE launch (fp16 inputs), DOUBLE-BUFFERED staging.
// blocks: proj3 0..63 (ksplit, atomic) | proj2 64..127 | proj1 128..383
// ---------------------------------------------------------------------------
#define PAST 72
#define PWST 264
#define PBUF (64 * PAST + 64 * PWST)   // halfs per buffer

__global__ __launch_bounds__(256) void projall_kernel(
    const __half* __restrict__ hf1, const __half* __restrict__ hw1,
    const float* __restrict__ b1, float* __restrict__ p1, __half* __restrict__ x1,
    const __half* __restrict__ hf2, const __half* __restrict__ hw2,
    const float* __restrict__ b2, __half* __restrict__ x2,
    const __half* __restrict__ hf3, const __half* __restrict__ hw3,
    float* __restrict__ x3)
{
    extern __shared__ char smbuf[];
    __half* base0 = (__half*)smbuf;

    const int bi = blockIdx.x;
    const __half *A, *W; const float* bias = nullptr;
    int KDIM, kbase = 0, kd, row0;
    float* outF = nullptr; __half* outH = nullptr; int atomicF = 0;
    if (bi < 64) {
        int s = bi;
        A = hf3; W = hw3; KDIM = 1024; kd = 256; kbase = (s >> 4) * 256;
        row0 = (s & 15) * 64; outF = x3; atomicF = 1;
    } else if (bi < 128) {
        A = hf2; W = hw2; bias = b2; KDIM = 512; kd = 512;
        row0 = (bi - 64) * 64; outH = x2;
    } else {
        A = hf1; W = hw1; bias = b1; KDIM = 256; kd = 256;
        row0 = (bi - 128) * 64; outF = p1; outH = x1;
    }

    const int t = threadIdx.x, w = t >> 5, l = t & 31;
    const int wr = w >> 2, wc = w & 3;
    const int aRow = l & 15, aCol = (l >> 4) * 8;

    float acc[2][8][4];
#pragma unroll
    for (int mf = 0; mf < 2; mf++)
#pragma unroll
        for (int nf = 0; nf < 8; nf++)
#pragma unroll
            for (int e = 0; e < 4; e++) acc[mf][nf][e] = 0.f;

    const int nIter = kd >> 6;

#define PSTAGE(BUF, KG) do {                                                   \
    __half* sA_ = base0 + (BUF) * PBUF;                                        \
    __half* sW_ = sA_ + 64 * PAST;                                             \
    for (int idx = t; idx < 512; idx += 256) {                                 \
        int r_ = idx >> 3, c_ = idx & 7;                                       \
        *(uint4*)(sA_ + r_ * PAST + c_ * 8) =                                  \
            *(const uint4*)(A + (size_t)(row0 + r_) * KDIM + (KG) + c_ * 8);   \
    }                                                                          \
    for (int idx = t; idx < 2048; idx += 256) {                                \
        int r_ = idx >> 5, c_ = idx & 31;                                      \
        *(uint4*)(sW_ + r_ * PWST + c_ * 8) =                                  \
            *(const uint4*)(W + (size_t)((KG) + r_) * 256 + c_ * 8);           \
    }                                                                          \
} while (0)

    PSTAGE(0, kbase);
    __syncthreads();

    for (int it = 0; it < nIter; it++) {
        const int cb = it & 1;
        if (it + 1 < nIter) PSTAGE(cb ^ 1, kbase + (it + 1) * 64);
        const uint32_t sa0 = smem_u32(base0 + cb * PBUF);
        const uint32_t sw0 = sa0 + 64 * PAST * 2;
#pragma unroll
        for (int ks = 0; ks < 4; ks++) {
            uint32_t a[2][4];
#pragma unroll
            for (int mf = 0; mf < 2; mf++) {
                uint32_t off = (uint32_t)((wr * 32 + mf * 16 + aRow) * PAST +
                                          ks * 16 + aCol) * 2;
                ldsm4(a[mf], sa0 + off);
            }
#pragma unroll
            for (int p = 0; p < 4; p++) {
                uint32_t bfr[4];
                uint32_t off = (uint32_t)((ks * 16 + aRow) * PWST +
                                          wc * 64 + p * 16 + aCol) * 2;
                ldsm4t(bfr, sw0 + off);
#pragma unroll
                for (int mf = 0; mf < 2; mf++) {
                    mma_f16(acc[mf][p * 2 + 0], a[mf], &bfr[0]);
                    mma_f16(acc[mf][p * 2 + 1], a[mf], &bfr[2]);
                }
            }
        }
        __syncthreads();
    }

#pragma unroll
    for (int mf = 0; mf < 2; mf++)
#pragma unroll
    for (int nf = 0; nf < 8; nf++)
#pragma unroll
    for (int pr = 0; pr < 2; pr++) {
        int r = row0 + wr * 32 + mf * 16 + (l >> 2) + pr * 8;
        int c = wc * 64 + nf * 8 + (l & 3) * 2;
        float v0 = acc[mf][nf][pr * 2 + 0];
        float v1 = acc[mf][nf][pr * 2 + 1];
        if (atomicF) {
            atomicAdd(outF + (size_t)r * 256 + c,     v0);
            atomicAdd(outF + (size_t)r * 256 + c + 1, v1);
        } else {
            v0 += bias[c]; v1 += bias[c + 1];
            if (outF) *(float2*)(outF + (size_t)r * 256 + c) = make_float2(v0, v1);
            *(uint32_t*)(outH + (size_t)r * 256 + c) =
                pack_h(__float2half_rn(v0), __float2half_rn(v1));
        }
    }
}

// ---------------------------------------------------------------------------
// gram att2 (fp16 MMA, blocks 0..63) + att3 gram (fp32, blocks 64..79)
// ---------------------------------------------------------------------------
__global__ __launch_bounds__(256) void gram_att3_kernel(
    const __half* __restrict__ X2, float* __restrict__ att2,
    const float* __restrict__ X3, float* __restrict__ att3)
{
    constexpr int XST = 72;
    extern __shared__ char smbuf[];

    if (blockIdx.x < 64) {
        __half* sI = (__half*)smbuf;
        __half* sJ = sI + 128 * XST;
        const int idx0 = blockIdx.x;
        const int b = idx0 >> 2;
        const int i0 = ((idx0 >> 1) & 1) * 128, j0 = (idx0 & 1) * 128;
        const int t = threadIdx.x, w = t >> 5, l = t & 31;
        const int wr = w >> 1, wc = w & 1;
        const int aRow = l & 15, aCol = (l >> 4) * 8;
        const int bRow = (l >> 4) * 8 + (l & 7), bCol = ((l >> 3) & 1) * 8;
        const __half* Xb = X2 + (size_t)b * 256 * CCH;

        float acc[2][8][4];
#pragma unroll
        for (int mf = 0; mf < 2; mf++)
#pragma unroll
            for (int nf = 0; nf < 8; nf++)
#pragma unroll
                for (int e = 0; e < 4; e++) acc[mf][nf][e] = 0.f;

        const uint32_t si0 = smem_u32(sI), sj0 = smem_u32(sJ);

        for (int kb = 0; kb < CCH; kb += 64) {
            __syncthreads();
            for (int idx = t; idx < 128 * 8; idx += 256) {
                int r = idx >> 3, c = idx & 7;
                *(uint4*)(sI + r * XST + c * 8) =
                    *(const uint4*)(Xb + (size_t)(i0 + r) * CCH + kb + c * 8);
                *(uint4*)(sJ + r * XST + c * 8) =
                    *(const uint4*)(Xb + (size_t)(j0 + r) * CCH + kb + c * 8);
            }
            __syncthreads();
#pragma unroll
            for (int ks = 0; ks < 4; ks++) {
                uint32_t a[2][4];
#pragma unroll
                for (int mf = 0; mf < 2; mf++) {
                    uint32_t off = (uint32_t)((wr * 32 + mf * 16 + aRow) * XST +
                                              ks * 16 + aCol) * 2;
                    ldsm4(a[mf], si0 + off);
                }
#pragma unroll
                for (int bt = 0; bt < 4; bt++) {
                    uint32_t bfr[4];
                    uint32_t off = (uint32_t)((wc * 64 + bt * 16 + bRow) * XST +
                                              ks * 16 + bCol) * 2;
                    ldsm4(bfr, sj0 + off);
#pragma unroll
                    for (int mf = 0; mf < 2; mf++) {
                        mma_f16(acc[mf][bt * 2 + 0], a[mf], &bfr[0]);
                        mma_f16(acc[mf][bt * 2 + 1], a[mf], &bfr[2]);
                    }
                }
            }
        }

#pragma unroll
        for (int mf = 0; mf < 2; mf++)
#pragma unroll
        for (int nf = 0; nf < 8; nf++)
#pragma unroll
        for (int pr = 0; pr < 2; pr++) {
            int i = i0 + wr * 32 + mf * 16 + (l >> 2) + pr * 8;
            int j = j0 + wc * 64 + nf * 8 + (l & 3) * 2;
            *(float2*)(att2 + (size_t)b * 256 * 256 + (size_t)i * 256 + j) =
                make_float2(acc[mf][nf][pr * 2 + 0], acc[mf][nf][pr * 2 + 1]);
        }
    } else {
        float* Ai = (float*)smbuf;
        const int b = blockIdx.x - 64;
        const int t = threadIdx.x;
        const int ty = t >> 4, tx = t & 15;
        const int r0 = ty * 4, c0 = tx * 4;
        const float* Xb = X3 + (size_t)b * 64 * CCH;

        float acc[4][4] = {};
        for (int k0 = 0; k0 < CCH; k0 += 32) {
            __syncthreads();
#pragma unroll
            for (int i = 0; i < 8; i++) {
                int lin = t + 256 * i;
                int r = lin >> 5, k = lin & 31;
                Ai[k * 65 + r] = Xb[(size_t)r * CCH + k0 + k];
            }
            __syncthreads();
#pragma unroll
            for (int k = 0; k < 32; k++) {
                float a[4], bb[4];
#pragma unroll
                for (int i = 0; i < 4; i++) a[i]  = Ai[k * 65 + r0 + i];
#pragma unroll
                for (int j = 0; j < 4; j++) bb[j] = Ai[k * 65 + c0 + j];
#pragma unroll
                for (int i = 0; i < 4; i++)
#pragma unroll
                    for (int j = 0; j < 4; j++)
                        acc[i][j] += a[i] * bb[j];
            }
        }
#pragma unroll
        for (int i = 0; i < 4; i++) {
            float4 o = make_float4(acc[i][0], acc[i][1], acc[i][2], acc[i][3]);
            *(float4*)&att3[(size_t)b * 64 * 64 + (size_t)(r0 + i) * 64 + c0] = o;
        }
    }
}

// ---------------------------------------------------------------------------
// Fused sigmoid-attention (round-14 version, no register prefetch):
// 128x128 tiles, 512 threads, grid 128; raw fp16 S round-trip + cheap gate.
// ---------------------------------------------------------------------------
#define KST 264
#define SST 136

__global__ __launch_bounds__(512, 1) void fused_mma_kernel(
    const __half* __restrict__ x1,
    const float* __restrict__ p1,
    const float* __restrict__ att2, const float* __restrict__ att3,
    const float* __restrict__ pa1, const float* __restrict__ pa2,
    const float* __restrict__ pa3, float* __restrict__ out)
{
    extern __shared__ char smbuf[];
    __half* Qs = (__half*)smbuf;            // 128 x 264
    __half* Ks = Qs + 128 * KST;            // 128 x 264
    __half* Ss = Ks + 128 * KST;            // 128 x 136
    float* A2s = (float*)(Ss + 128 * SST);  // 33 x 257 (x a2)
    float* A3s = A2s + 33 * 257;            // 9 x 65  (x a3)

    const int b  = blockIdx.y;
    const int n0 = blockIdx.x * 128;
    const int t  = threadIdx.x, w = t >> 5, l = t & 31;
    const int wn = w & 3, wc = w >> 2;
    const int aRow = l & 15, aCol = (l >> 4) * 8;
    const int bRow = (l >> 4) * 8 + (l & 7);
    const int bCol = ((l >> 3) & 1) * 8;

    const __half* Xb = x1 + (size_t)b * N1D * CCH;
    const float sa1 = *pa1, sa2 = *pa2, sa3 = *pa3;
    const int r2lo = n0 >> 2, r3lo = n0 >> 4;

#pragma unroll
    for (int i = 0; i < 8; i++) {
        int idx = t + 512 * i;
        int r = idx >> 5, c = idx & 31;
        *(uint4*)(Qs + r * KST + c * 8) =
            *(const uint4*)(Xb + (size_t)(n0 + r) * CCH + c * 8);
    }
    for (int i = t; i < 33 * 256; i += 512) {
        int rr = i >> 8, cc = i & 255;
        A2s[rr * 257 + cc] =
            sa2 * att2[((size_t)b * 256 + min(r2lo + rr, 255)) * 256 + cc];
    }
    for (int i = t; i < 9 * 64; i += 512) {
        int rr = i >> 6, cc = i & 63;
        A3s[rr * 65 + cc] =
            sa3 * att3[((size_t)b * 64 + min(r3lo + rr, 63)) * 64 + cc];
    }

    const uint32_t q0 = smem_u32(Qs);
    const uint32_t k0 = smem_u32(Ks);
    const uint32_t s0 = smem_u32(Ss);

    // gate-pass constants
    const int grow = t >> 2, gcq = t & 3;
    const int gn = n0 + grow;
    const int grn = gn >> 2;
    const float gfn = (float)(gn & 3) * 0.25f;
    const float* GR0 = A2s + (grn - r2lo) * 257;
    const float* GR1 = A2s + (min(grn + 1, 255) - r2lo) * 257;
    const int grn3 = gn >> 4;
    const float gfn3 = (float)(gn & 15) * 0.0625f;
    const float* GT0 = A3s + (grn3 - r3lo) * 65;
    const float* GT1 = A3s + (min(grn3 + 1, 63) - r3lo) * 65;
    __half* Srow = Ss + grow * SST + gcq * 32;

    float O[2][8][4];
#pragma unroll
    for (int mf = 0; mf < 2; mf++)
#pragma unroll
        for (int f = 0; f < 8; f++)
#pragma unroll
            for (int e = 0; e < 4; e++) O[mf][f][e] = 0.f;

    for (int mt = 0; mt < 8; mt++) {
        const int m0 = mt * 128;
        __syncthreads();
#pragma unroll
        for (int i = 0; i < 8; i++) {
            int idx = t + 512 * i;
            int r = idx >> 5, c = idx & 31;
            *(uint4*)(Ks + r * KST + c * 8) =
                *(const uint4*)(Xb + (size_t)(m0 + r) * CCH + c * 8);
        }
        __syncthreads();

        // ---- GEMM1: S(128x128) = Q . K^T ----
        float Sa[2][4][4];
#pragma unroll
        for (int mf = 0; mf < 2; mf++)
#pragma unroll
            for (int nf = 0; nf < 4; nf++)
#pragma unroll
                for (int e = 0; e < 4; e++) Sa[mf][nf][e] = 0.f;

#pragma unroll
        for (int kc = 0; kc < 16; kc++) {
            uint32_t a[2][4];
#pragma unroll
            for (int mf = 0; mf < 2; mf++) {
                uint32_t offA = (uint32_t)((wn * 32 + mf * 16 + aRow) * KST +
                                           kc * 16 + aCol) * 2;
                ldsm4(a[mf], q0 + offA);
            }
            uint32_t bf[4][2];
#pragma unroll
            for (int bt = 0; bt < 2; bt++) {
                uint32_t r[4];
                uint32_t offB = (uint32_t)((wc * 32 + bt * 16 + bRow) * KST +
                                           kc * 16 + bCol) * 2;
                ldsm4(r, k0 + offB);
                bf[bt * 2][0] = r[0]; bf[bt * 2][1] = r[1];
                bf[bt * 2 + 1][0] = r[2]; bf[bt * 2 + 1][1] = r[3];
            }
#pragma unroll
            for (int mf = 0; mf < 2; mf++)
#pragma unroll
                for (int nf = 0; nf < 4; nf++)
                    mma_f16(Sa[mf][nf], a[mf], bf[nf]);
        }

        // ---- write raw S (fp16) ----
#pragma unroll
        for (int mf = 0; mf < 2; mf++)
#pragma unroll
        for (int nf = 0; nf < 4; nf++)
#pragma unroll
        for (int pr = 0; pr < 2; pr++) {
            int row_l = wn * 32 + mf * 16 + (l >> 2) + pr * 8;
            int col_l = wc * 32 + nf * 8 + (l & 3) * 2;
            *(uint32_t*)&Ss[row_l * SST + col_l] =
                pack_h(__float2half_rn(Sa[mf][nf][pr * 2 + 0]),
                       __float2half_rn(Sa[mf][nf][pr * 2 + 1]));
        }
        __syncthreads();

        // ---- gate pass: row-contiguous, in-place ----
        {
            const int mbase = m0 + gcq * 32;
            float ta = 0.f, td = 0.f;
#pragma unroll
            for (int s = 0; s < 4; s++) {
                const int mb = mbase + s * 8;
                if ((s & 1) == 0) {
                    int c3  = mb >> 4;
                    int c31 = min(c3 + 1, 63);
                    float t0v = GT0[c3]  + gfn3 * (GT1[c3]  - GT0[c3]);
                    float t1v = GT0[c31] + gfn3 * (GT1[c31] - GT0[c31]);
                    ta = t0v;
                    td = (t1v - t0v) * 0.0625f;
                }
                const int cm  = mb >> 2;
                const int cmc = min(cm + 2, 255);
                float la = GR0[cm]     + gfn * (GR1[cm]     - GR0[cm]);
                float lb = GR0[cm + 1] + gfn * (GR1[cm + 1] - GR0[cm + 1]);
                float lc = GR0[cmc]    + gfn * (GR1[cmc]    - GR0[cmc]);
                float d0 = (lb - la) * 0.25f;
                float d1 = (lc - lb) * 0.25f;
                const float c16 = (float)((s & 1) * 8);

                uint4 raw = *(uint4*)(Srow + s * 8);
                uint32_t rw[4] = {raw.x, raw.y, raw.z, raw.w};
                uint32_t ow[4];
#pragma unroll
                for (int pj = 0; pj < 4; pj++) {
                    float2 sv = __half22float2(*(__half2*)&rw[pj]);
                    float res[2];
#pragma unroll
                    for (int e = 0; e < 2; e++) {
                        int j = pj * 2 + e;
                        float base = (j < 4) ? la : lb;
                        float dd   = (j < 4) ? d0 : d1;
                        float v2 = base + (float)(j & 3) * dd;
                        float v3 = ta + (c16 + (float)j) * td;
                        float Sv = (e == 0) ? sv.x : sv.y;
                        float val = fmaf(sa1, Sv, v2 + v3);
                        res[e] = 1.0f / (1.0f + __expf(-val));
                    }
                    ow[pj] = pack_h(__float2half_rn(res[0]),
                                    __float2half_rn(res[1]));
                }
                *(uint4*)(Srow + s * 8) = make_uint4(ow[0], ow[1], ow[2], ow[3]);
            }
        }
        __syncthreads();

        // ---- GEMM2: O(128x256) += S(128x128) . K(128x256) ----
#pragma unroll
        for (int kc = 0; kc < 8; kc++) {
            uint32_t sA[2][4];
#pragma unroll
            for (int mf = 0; mf < 2; mf++) {
                uint32_t offA = (uint32_t)((wn * 32 + mf * 16 + aRow) * SST +
                                           kc * 16 + aCol) * 2;
                ldsm4(sA[mf], s0 + offA);
            }
#pragma unroll
            for (int p = 0; p < 4; p++) {
                uint32_t r[4];
                uint32_t offB = (uint32_t)((kc * 16 + aRow) * KST +
                                           wc * 64 + p * 16 + aCol) * 2;
                ldsm4t(r, k0 + offB);
#pragma unroll
                for (int mf = 0; mf < 2; mf++) {
                    mma_f16(O[mf][p * 2 + 0], sA[mf], &r[0]);
                    mma_f16(O[mf][p * 2 + 1], sA[mf], &r[2]);
                }
            }
        }
    }

    // ---- final: out = O + p1 ----
#pragma unroll
    for (int mf = 0; mf < 2; mf++)
#pragma unroll
    for (int f = 0; f < 8; f++)
#pragma unroll
    for (int pr = 0; pr < 2; pr++) {
        const int n  = n0 + wn * 32 + mf * 16 + (l >> 2) + pr * 8;
        const int ch = wc * 64 + f * 8 + (l & 3) * 2;
        const size_t o = ((size_t)(b * N1D + n)) * CCH + ch;
        float2 pv = *(const float2*)(p1 + o);
        *(float2*)(out + o) = make_float2(O[mf][f][pr * 2 + 0] + pv.x,
                                          O[mf][f][pr * 2 + 1] + pv.y);
    }
}

// ---------------------------------------------------------------------------
extern "C" void kernel_launch(void* const* d_in, const int* in_sizes, int n_in,
                              void* d_out, int out_size)
{
    const float* f1 = (const float*)d_in[0];
    const float* f2 = (const float*)d_in[1];
    const float* f3 = (const float*)d_in[2];
    const float* w1 = (const float*)d_in[3];
    const float* b1 = (const float*)d_in[4];
    const float* w2 = (const float*)d_in[5];
    const float* b2 = (const float*)d_in[6];
    const float* w3 = (const float*)d_in[7];
    const float* b3 = (const float*)d_in[8];
    const float* a1 = (const float*)d_in[9];
    const float* a2 = (const float*)d_in[10];
    const float* a3 = (const float*)d_in[11];
    float* out = (float*)d_out;

    float *p1, *x3, *att2, *att3;
    __half *x1, *x2, *hf1, *hf2, *hf3, *hw1, *hw2, *hw3;
    cudaGetSymbolAddress((void**)&p1,   g_p1);
    cudaGetSymbolAddress((void**)&x3,   g_x3);
    cudaGetSymbolAddress((void**)&att2, g_att2);
    cudaGetSymbolAddress((void**)&att3, g_att3);
    cudaGetSymbolAddress((void**)&x1,   g_x1);
    cudaGetSymbolAddress((void**)&x2,   g_x2);
    cudaGetSymbolAddress((void**)&hf1,  g_f1);
    cudaGetSymbolAddress((void**)&hf2,  g_f2);
    cudaGetSymbolAddress((void**)&hf3,  g_f3);
    cudaGetSymbolAddress((void**)&hw1,  g_w1);
    cudaGetSymbolAddress((void**)&hw2,  g_w2);
    cudaGetSymbolAddress((void**)&hw3,  g_w3);

    cvt_all_kernel<<<7872, 256>>>(f1, f2, f3, w1, w2, w3, b3,
                                  hf1, hf2, hf3, hw1, hw2, hw3, x3);

    const int smemP = PBUF * 2 * 2;   // two buffers, halfs->bytes
    cudaFuncSetAttribute(projall_kernel,
                         cudaFuncAttributeMaxDynamicSharedMemorySize, smemP);
    projall_kernel<<<384, 256, smemP>>>(hf1, hw1, b1, p1, x1,
                                        hf2, hw2, b2, x2,
                                        hf3, hw3, x3);

    const int smemG = 2 * 128 * 72 * 2;
    cudaFuncSetAttribute(gram_att3_kernel,
                         cudaFuncAttributeMaxDynamicSharedMemorySize, smemG);
    gram_att3_kernel<<<80, 256, smemG>>>(x2, att2, x3, att3);

    const int smemF = (128 * KST * 2 + 128 * SST) * 2
                      + (33 * 257 + 9 * 65) * 4;
    cudaFuncSetAttribute(fused_mma_kernel,
                         cudaFuncAttributeMaxDynamicSharedMemorySize, smemF);
    fused_mma_kernel<<<dim3(8, BATCH), 512, smemF>>>(
        x1, p1, att2, att3, a1, a2, a3, out);
}

// round 17
// speedup vs baseline: 1.1558x; 1.1040x over previous
#include <cuda_runtime.h>
#include <cuda_fp16.h>
#include <math.h>
#include <stdint.h>

#define BATCH 16
#define N1D 1024
#define CCH 256

// ---------------- device scratch ----------------
__device__ float g_p1[BATCH * N1D * CCH];
__device__ float g_x3[BATCH * 64 * CCH];
__device__ float g_att2[BATCH * 256 * 256];
__device__ float g_att3[BATCH * 64 * 64];
__device__ __half g_x1[BATCH * N1D * CCH];
__device__ __half g_x2[BATCH * 256 * CCH];
__device__ __half g_f1[BATCH * N1D * CCH];
__device__ __half g_f2[BATCH * 256 * 512];
__device__ __half g_f3[BATCH * 64 * 1024];
__device__ __half g_w1[256 * 256];
__device__ __half g_w2[512 * 256];
__device__ __half g_w3[1024 * 256];

// ---------------- warp-MMA helpers ----------------
__device__ __forceinline__ uint32_t smem_u32(const void* p) {
    uint32_t a;
    asm("{ .reg .u64 t; cvta.to.shared.u64 t, %1; cvt.u32.u64 %0, t; }"
        : "=r"(a) : "l"(p));
    return a;
}
__device__ __forceinline__ void ldsm4(uint32_t* r, uint32_t a) {
    asm volatile("ldmatrix.sync.aligned.m8n8.x4.shared.b16 {%0,%1,%2,%3}, [%4];"
        : "=r"(r[0]), "=r"(r[1]), "=r"(r[2]), "=r"(r[3]) : "r"(a));
}
__device__ __forceinline__ void ldsm4t(uint32_t* r, uint32_t a) {
    asm volatile("ldmatrix.sync.aligned.m8n8.x4.trans.shared.b16 {%0,%1,%2,%3}, [%4];"
        : "=r"(r[0]), "=r"(r[1]), "=r"(r[2]), "=r"(r[3]) : "r"(a));
}
__device__ __forceinline__ void mma_f16(float* d, const uint32_t* a,
                                        const uint32_t* b) {
    asm volatile(
        "mma.sync.aligned.m16n8k16.row.col.f32.f16.f16.f32 "
        "{%0,%1,%2,%3}, {%4,%5,%6,%7}, {%8,%9}, {%0,%1,%2,%3};"
        : "+f"(d[0]), "+f"(d[1]), "+f"(d[2]), "+f"(d[3])
        : "r"(a[0]), "r"(a[1]), "r"(a[2]), "r"(a[3]), "r"(b[0]), "r"(b[1]));
}
__device__ __forceinline__ unsigned pack_h(__half a, __half b) {
    return ((unsigned)__half_as_ushort(b) << 16) | (unsigned)__half_as_ushort(a);
}

// ---------------------------------------------------------------------------
// cvt + bias-init in ONE launch.
// ---------------------------------------------------------------------------
__global__ void cvt_all_kernel(
    const float* __restrict__ f1, const float* __restrict__ f2,
    const float* __restrict__ f3, const float* __restrict__ w1,
    const float* __restrict__ w2, const float* __restrict__ w3,
    const float* __restrict__ b3,
    __half* __restrict__ o1, __half* __restrict__ o2, __half* __restrict__ o3,
    __half* __restrict__ o4, __half* __restrict__ o5, __half* __restrict__ o6,
    float* __restrict__ x3)
{
    int bi = blockIdx.x;
    if (bi >= 7616) {
        int idx = (bi - 7616) * 256 + threadIdx.x;
        int cj = idx & 63;
        float4 bv = *(const float4*)&b3[cj * 4];
        *(float4*)&x3[idx * 4] = bv;
        return;
    }
    const float* src; __half* dst; int base;
    if      (bi < 4096) { src = f1; dst = o1; base = 0; }
    else if (bi < 6144) { src = f2; dst = o2; base = 4096; }
    else if (bi < 7168) { src = f3; dst = o3; base = 6144; }
    else if (bi < 7232) { src = w1; dst = o4; base = 7168; }
    else if (bi < 7360) { src = w2; dst = o5; base = 7232; }
    else                { src = w3; dst = o6; base = 7360; }
    size_t i4 = (size_t)(bi - base) * 256 + threadIdx.x;
    float4 v = *(const float4*)(src + i4 * 4);
    uint2 o;
    o.x = pack_h(__float2half_rn(v.x), __float2half_rn(v.y));
    o.y = pack_h(__float2half_rn(v.z), __float2half_rn(v.w));
    *(uint2*)(dst + i4 * 4) = o;
}

// ---------------------------------------------------------------------------
// ALL projections in ONE launch (fp16 inputs), single-buffered (round-14).
// blocks: proj3 0..63 (ksplit, atomic) | proj2 64..127 | proj1 128..383
// ---------------------------------------------------------------------------
__global__ __launch_bounds__(256) void projall_kernel(
    const __half* __restrict__ hf1, const __half* __restrict__ hw1,
    const float* __restrict__ b1, float* __restrict__ p1, __half* __restrict__ x1,
    const __half* __restrict__ hf2, const __half* __restrict__ hw2,
    const float* __restrict__ b2, __half* __restrict__ x2,
    const __half* __restrict__ hf3, const __half* __restrict__ hw3,
    float* __restrict__ x3)
{
    constexpr int AST = 72, WST = 264;
    extern __shared__ char smbuf[];
    __half* sA = (__half*)smbuf;
    __half* sW = sA + 64 * AST;

    const int bi = blockIdx.x;
    const __half *A, *W; const float* bias = nullptr;
    int KDIM, kbase = 0, kd, row0;
    float* outF = nullptr; __half* outH = nullptr; int atomicF = 0;
    if (bi < 64) {
        int s = bi;
        A = hf3; W = hw3; KDIM = 1024; kd = 256; kbase = (s >> 4) * 256;
        row0 = (s & 15) * 64; outF = x3; atomicF = 1;
    } else if (bi < 128) {
        A = hf2; W = hw2; bias = b2; KDIM = 512; kd = 512;
        row0 = (bi - 64) * 64; outH = x2;
    } else {
        A = hf1; W = hw1; bias = b1; KDIM = 256; kd = 256;
        row0 = (bi - 128) * 64; outF = p1; outH = x1;
    }

    const int t = threadIdx.x, w = t >> 5, l = t & 31;
    const int wr = w >> 2, wc = w & 3;
    const int aRow = l & 15, aCol = (l >> 4) * 8;

    float acc[2][8][4];
#pragma unroll
    for (int mf = 0; mf < 2; mf++)
#pragma unroll
        for (int nf = 0; nf < 8; nf++)
#pragma unroll
            for (int e = 0; e < 4; e++) acc[mf][nf][e] = 0.f;

    const uint32_t sa0 = smem_u32(sA), sw0 = smem_u32(sW);

    for (int kb = 0; kb < kd; kb += 64) {
        const int kg = kbase + kb;
        __syncthreads();
        for (int idx = t; idx < 64 * 8; idx += 256) {
            int r = idx >> 3, c = idx & 7;
            *(uint4*)(sA + r * AST + c * 8) =
                *(const uint4*)(A + (size_t)(row0 + r) * KDIM + kg + c * 8);
        }
        for (int idx = t; idx < 64 * 32; idx += 256) {
            int r = idx >> 5, c = idx & 31;
            *(uint4*)(sW + r * WST + c * 8) =
                *(const uint4*)(W + (size_t)(kg + r) * 256 + c * 8);
        }
        __syncthreads();
#pragma unroll
        for (int ks = 0; ks < 4; ks++) {
            uint32_t a[2][4];
#pragma unroll
            for (int mf = 0; mf < 2; mf++) {
                uint32_t off = (uint32_t)((wr * 32 + mf * 16 + aRow) * AST +
                                          ks * 16 + aCol) * 2;
                ldsm4(a[mf], sa0 + off);
            }
#pragma unroll
            for (int p = 0; p < 4; p++) {
                uint32_t bfr[4];
                uint32_t off = (uint32_t)((ks * 16 + aRow) * WST +
                                          wc * 64 + p * 16 + aCol) * 2;
                ldsm4t(bfr, sw0 + off);
#pragma unroll
                for (int mf = 0; mf < 2; mf++) {
                    mma_f16(acc[mf][p * 2 + 0], a[mf], &bfr[0]);
                    mma_f16(acc[mf][p * 2 + 1], a[mf], &bfr[2]);
                }
            }
        }
    }

#pragma unroll
    for (int mf = 0; mf < 2; mf++)
#pragma unroll
    for (int nf = 0; nf < 8; nf++)
#pragma unroll
    for (int pr = 0; pr < 2; pr++) {
        int r = row0 + wr * 32 + mf * 16 + (l >> 2) + pr * 8;
        int c = wc * 64 + nf * 8 + (l & 3) * 2;
        float v0 = acc[mf][nf][pr * 2 + 0];
        float v1 = acc[mf][nf][pr * 2 + 1];
        if (atomicF) {
            atomicAdd(outF + (size_t)r * 256 + c,     v0);
            atomicAdd(outF + (size_t)r * 256 + c + 1, v1);
        } else {
            v0 += bias[c]; v1 += bias[c + 1];
            if (outF) *(float2*)(outF + (size_t)r * 256 + c) = make_float2(v0, v1);
            *(uint32_t*)(outH + (size_t)r * 256 + c) =
                pack_h(__float2half_rn(v0), __float2half_rn(v1));
        }
    }
}

// ---------------------------------------------------------------------------
// gram att2 (fp16 MMA, blocks 0..63) + att3 gram (fp32, blocks 64..79)
// ---------------------------------------------------------------------------
__global__ __launch_bounds__(256) void gram_att3_kernel(
    const __half* __restrict__ X2, float* __restrict__ att2,
    const float* __restrict__ X3, float* __restrict__ att3)
{
    constexpr int XST = 72;
    extern __shared__ char smbuf[];

    if (blockIdx.x < 64) {
        __half* sI = (__half*)smbuf;
        __half* sJ = sI + 128 * XST;
        const int idx0 = blockIdx.x;
        const int b = idx0 >> 2;
        const int i0 = ((idx0 >> 1) & 1) * 128, j0 = (idx0 & 1) * 128;
        const int t = threadIdx.x, w = t >> 5, l = t & 31;
        const int wr = w >> 1, wc = w & 1;
        const int aRow = l & 15, aCol = (l >> 4) * 8;
        const int bRow = (l >> 4) * 8 + (l & 7), bCol = ((l >> 3) & 1) * 8;
        const __half* Xb = X2 + (size_t)b * 256 * CCH;

        float acc[2][8][4];
#pragma unroll
        for (int mf = 0; mf < 2; mf++)
#pragma unroll
            for (int nf = 0; nf < 8; nf++)
#pragma unroll
                for (int e = 0; e < 4; e++) acc[mf][nf][e] = 0.f;

        const uint32_t si0 = smem_u32(sI), sj0 = smem_u32(sJ);

        for (int kb = 0; kb < CCH; kb += 64) {
            __syncthreads();
            for (int idx = t; idx < 128 * 8; idx += 256) {
                int r = idx >> 3, c = idx & 7;
                *(uint4*)(sI + r * XST + c * 8) =
                    *(const uint4*)(Xb + (size_t)(i0 + r) * CCH + kb + c * 8);
                *(uint4*)(sJ + r * XST + c * 8) =
                    *(const uint4*)(Xb + (size_t)(j0 + r) * CCH + kb + c * 8);
            }
            __syncthreads();
#pragma unroll
            for (int ks = 0; ks < 4; ks++) {
                uint32_t a[2][4];
#pragma unroll
                for (int mf = 0; mf < 2; mf++) {
                    uint32_t off = (uint32_t)((wr * 32 + mf * 16 + aRow) * XST +
                                              ks * 16 + aCol) * 2;
                    ldsm4(a[mf], si0 + off);
                }
#pragma unroll
                for (int bt = 0; bt < 4; bt++) {
                    uint32_t bfr[4];
                    uint32_t off = (uint32_t)((wc * 64 + bt * 16 + bRow) * XST +
                                              ks * 16 + bCol) * 2;
                    ldsm4(bfr, sj0 + off);
#pragma unroll
                    for (int mf = 0; mf < 2; mf++) {
                        mma_f16(acc[mf][bt * 2 + 0], a[mf], &bfr[0]);
                        mma_f16(acc[mf][bt * 2 + 1], a[mf], &bfr[2]);
                    }
                }
            }
        }

#pragma unroll
        for (int mf = 0; mf < 2; mf++)
#pragma unroll
        for (int nf = 0; nf < 8; nf++)
#pragma unroll
        for (int pr = 0; pr < 2; pr++) {
            int i = i0 + wr * 32 + mf * 16 + (l >> 2) + pr * 8;
            int j = j0 + wc * 64 + nf * 8 + (l & 3) * 2;
            *(float2*)(att2 + (size_t)b * 256 * 256 + (size_t)i * 256 + j) =
                make_float2(acc[mf][nf][pr * 2 + 0], acc[mf][nf][pr * 2 + 1]);
        }
    } else {
        float* Ai = (float*)smbuf;
        const int b = blockIdx.x - 64;
        const int t = threadIdx.x;
        const int ty = t >> 4, tx = t & 15;
        const int r0 = ty * 4, c0 = tx * 4;
        const float* Xb = X3 + (size_t)b * 64 * CCH;

        float acc[4][4] = {};
        for (int k0 = 0; k0 < CCH; k0 += 32) {
            __syncthreads();
#pragma unroll
            for (int i = 0; i < 8; i++) {
                int lin = t + 256 * i;
                int r = lin >> 5, k = lin & 31;
                Ai[k * 65 + r] = Xb[(size_t)r * CCH + k0 + k];
            }
            __syncthreads();
#pragma unroll
            for (int k = 0; k < 32; k++) {
                float a[4], bb[4];
#pragma unroll
                for (int i = 0; i < 4; i++) a[i]  = Ai[k * 65 + r0 + i];
#pragma unroll
                for (int j = 0; j < 4; j++) bb[j] = Ai[k * 65 + c0 + j];
#pragma unroll
                for (int i = 0; i < 4; i++)
#pragma unroll
                    for (int j = 0; j < 4; j++)
                        acc[i][j] += a[i] * bb[j];
            }
        }
#pragma unroll
        for (int i = 0; i < 4; i++) {
            float4 o = make_float4(acc[i][0], acc[i][1], acc[i][2], acc[i][3]);
            *(float4*)&att3[(size_t)b * 64 * 64 + (size_t)(r0 + i) * 64 + c0] = o;
        }
    }
}

// ---------------------------------------------------------------------------
// Fused sigmoid-attention: 128x128 tiles, 512 threads, grid 128.
// Raw fp16 S round-trip + row-contiguous gate pass with __fdividef sigmoid.
// ---------------------------------------------------------------------------
#define KST 264
#define SST 136

__global__ __launch_bounds__(512, 1) void fused_mma_kernel(
    const __half* __restrict__ x1,
    const float* __restrict__ p1,
    const float* __restrict__ att2, const float* __restrict__ att3,
    const float* __restrict__ pa1, const float* __restrict__ pa2,
    const float* __restrict__ pa3, float* __restrict__ out)
{
    extern __shared__ char smbuf[];
    __half* Qs = (__half*)smbuf;            // 128 x 264
    __half* Ks = Qs + 128 * KST;            // 128 x 264
    __half* Ss = Ks + 128 * KST;            // 128 x 136
    float* A2s = (float*)(Ss + 128 * SST);  // 33 x 257 (x a2)
    float* A3s = A2s + 33 * 257;            // 9 x 65  (x a3)

    const int b  = blockIdx.y;
    const int n0 = blockIdx.x * 128;
    const int t  = threadIdx.x, w = t >> 5, l = t & 31;
    const int wn = w & 3, wc = w >> 2;
    const int aRow = l & 15, aCol = (l >> 4) * 8;
    const int bRow = (l >> 4) * 8 + (l & 7);
    const int bCol = ((l >> 3) & 1) * 8;

    const __half* Xb = x1 + (size_t)b * N1D * CCH;
    const float sa1 = *pa1, sa2 = *pa2, sa3 = *pa3;
    const int r2lo = n0 >> 2, r3lo = n0 >> 4;

#pragma unroll
    for (int i = 0; i < 8; i++) {
        int idx = t + 512 * i;
        int r = idx >> 5, c = idx & 31;
        *(uint4*)(Qs + r * KST + c * 8) =
            *(const uint4*)(Xb + (size_t)(n0 + r) * CCH + c * 8);
    }
    for (int i = t; i < 33 * 256; i += 512) {
        int rr = i >> 8, cc = i & 255;
        A2s[rr * 257 + cc] =
            sa2 * att2[((size_t)b * 256 + min(r2lo + rr, 255)) * 256 + cc];
    }
    for (int i = t; i < 9 * 64; i += 512) {
        int rr = i >> 6, cc = i & 63;
        A3s[rr * 65 + cc] =
            sa3 * att3[((size_t)b * 64 + min(r3lo + rr, 63)) * 64 + cc];
    }

    const uint32_t q0 = smem_u32(Qs);
    const uint32_t k0 = smem_u32(Ks);
    const uint32_t s0 = smem_u32(Ss);

    // gate-pass constants
    const int grow = t >> 2, gcq = t & 3;
    const int gn = n0 + grow;
    const int grn = gn >> 2;
    const float gfn = (float)(gn & 3) * 0.25f;
    const float* GR0 = A2s + (grn - r2lo) * 257;
    const float* GR1 = A2s + (min(grn + 1, 255) - r2lo) * 257;
    const int grn3 = gn >> 4;
    const float gfn3 = (float)(gn & 15) * 0.0625f;
    const float* GT0 = A3s + (grn3 - r3lo) * 65;
    const float* GT1 = A3s + (min(grn3 + 1, 63) - r3lo) * 65;
    __half* Srow = Ss + grow * SST + gcq * 32;

    float O[2][8][4];
#pragma unroll
    for (int mf = 0; mf < 2; mf++)
#pragma unroll
        for (int f = 0; f < 8; f++)
#pragma unroll
            for (int e = 0; e < 4; e++) O[mf][f][e] = 0.f;

    for (int mt = 0; mt < 8; mt++) {
        const int m0 = mt * 128;
        __syncthreads();
#pragma unroll
        for (int i = 0; i < 8; i++) {
            int idx = t + 512 * i;
            int r = idx >> 5, c = idx & 31;
            *(uint4*)(Ks + r * KST + c * 8) =
                *(const uint4*)(Xb + (size_t)(m0 + r) * CCH + c * 8);
        }
        __syncthreads();

        // ---- GEMM1: S(128x128) = Q . K^T ----
        float Sa[2][4][4];
#pragma unroll
        for (int mf = 0; mf < 2; mf++)
#pragma unroll
            for (int nf = 0; nf < 4; nf++)
#pragma unroll
                for (int e = 0; e < 4; e++) Sa[mf][nf][e] = 0.f;

#pragma unroll
        for (int kc = 0; kc < 16; kc++) {
            uint32_t a[2][4];
#pragma unroll
            for (int mf = 0; mf < 2; mf++) {
                uint32_t offA = (uint32_t)((wn * 32 + mf * 16 + aRow) * KST +
                                           kc * 16 + aCol) * 2;
                ldsm4(a[mf], q0 + offA);
            }
            uint32_t bf[4][2];
#pragma unroll
            for (int bt = 0; bt < 2; bt++) {
                uint32_t r[4];
                uint32_t offB = (uint32_t)((wc * 32 + bt * 16 + bRow) * KST +
                                           kc * 16 + bCol) * 2;
                ldsm4(r, k0 + offB);
                bf[bt * 2][0] = r[0]; bf[bt * 2][1] = r[1];
                bf[bt * 2 + 1][0] = r[2]; bf[bt * 2 + 1][1] = r[3];
            }
#pragma unroll
            for (int mf = 0; mf < 2; mf++)
#pragma unroll
                for (int nf = 0; nf < 4; nf++)
                    mma_f16(Sa[mf][nf], a[mf], bf[nf]);
        }

        // ---- write raw S (fp16) ----
#pragma unroll
        for (int mf = 0; mf < 2; mf++)
#pragma unroll
        for (int nf = 0; nf < 4; nf++)
#pragma unroll
        for (int pr = 0; pr < 2; pr++) {
            int row_l = wn * 32 + mf * 16 + (l >> 2) + pr * 8;
            int col_l = wc * 32 + nf * 8 + (l & 3) * 2;
            *(uint32_t*)&Ss[row_l * SST + col_l] =
                pack_h(__float2half_rn(Sa[mf][nf][pr * 2 + 0]),
                       __float2half_rn(Sa[mf][nf][pr * 2 + 1]));
        }
        __syncthreads();

        // ---- gate pass: row-contiguous, in-place ----
        {
            const int mbase = m0 + gcq * 32;
            float ta = 0.f, td = 0.f;
#pragma unroll
            for (int s = 0; s < 4; s++) {
                const int mb = mbase + s * 8;
                if ((s & 1) == 0) {
                    int c3  = mb >> 4;
                    int c31 = min(c3 + 1, 63);
                    float t0v = GT0[c3]  + gfn3 * (GT1[c3]  - GT0[c3]);
                    float t1v = GT0[c31] + gfn3 * (GT1[c31] - GT0[c31]);
                    ta = t0v;
                    td = (t1v - t0v) * 0.0625f;
                }
                const int cm  = mb >> 2;
                const int cmc = min(cm + 2, 255);
                float la = GR0[cm]     + gfn * (GR1[cm]     - GR0[cm]);
                float lb = GR0[cm + 1] + gfn * (GR1[cm + 1] - GR0[cm + 1]);
                float lc = GR0[cmc]    + gfn * (GR1[cmc]    - GR0[cmc]);
                float d0 = (lb - la) * 0.25f;
                float d1 = (lc - lb) * 0.25f;
                const float c16 = (float)((s & 1) * 8);

                uint4 raw = *(uint4*)(Srow + s * 8);
                uint32_t rw[4] = {raw.x, raw.y, raw.z, raw.w};
                uint32_t ow[4];
#pragma unroll
                for (int pj = 0; pj < 4; pj++) {
                    float2 sv = __half22float2(*(__half2*)&rw[pj]);
                    float res[2];
#pragma unroll
                    for (int e = 0; e < 2; e++) {
                        int j = pj * 2 + e;
                        float base = (j < 4) ? la : lb;
                        float dd   = (j < 4) ? d0 : d1;
                        float v2 = base + (float)(j & 3) * dd;
                        float v3 = ta + (c16 + (float)j) * td;
                        float Sv = (e == 0) ? sv.x : sv.y;
                        float val = fmaf(sa1, Sv, v2 + v3);
                        res[e] = __fdividef(1.0f, 1.0f + __expf(-val));
                    }
                    ow[pj] = pack_h(__float2half_rn(res[0]),
                                    __float2half_rn(res[1]));
                }
                *(uint4*)(Srow + s * 8) = make_uint4(ow[0], ow[1], ow[2], ow[3]);
            }
        }
        __syncthreads();

        // ---- GEMM2: O(128x256) += S(128x128) . K(128x256) ----
#pragma unroll
        for (int kc = 0; kc < 8; kc++) {
            uint32_t sA[2][4];
#pragma unroll
            for (int mf = 0; mf < 2; mf++) {
                uint32_t offA = (uint32_t)((wn * 32 + mf * 16 + aRow) * SST +
                                           kc * 16 + aCol) * 2;
                ldsm4(sA[mf], s0 + offA);
            }
#pragma unroll
            for (int p = 0; p < 4; p++) {
                uint32_t r[4];
                uint32_t offB = (uint32_t)((kc * 16 + aRow) * KST +
                                           wc * 64 + p * 16 + aCol) * 2;
                ldsm4t(r, k0 + offB);
#pragma unroll
                for (int mf = 0; mf < 2; mf++) {
                    mma_f16(O[mf][p * 2 + 0], sA[mf], &r[0]);
                    mma_f16(O[mf][p * 2 + 1], sA[mf], &r[2]);
                }
            }
        }
    }

    // ---- final: out = O + p1 ----
#pragma unroll
    for (int mf = 0; mf < 2; mf++)
#pragma unroll
    for (int f = 0; f < 8; f++)
#pragma unroll
    for (int pr = 0; pr < 2; pr++) {
        const int n  = n0 + wn * 32 + mf * 16 + (l >> 2) + pr * 8;
        const int ch = wc * 64 + f * 8 + (l & 3) * 2;
        const size_t o = ((size_t)(b * N1D + n)) * CCH + ch;
        float2 pv = *(const float2*)(p1 + o);
        *(float2*)(out + o) = make_float2(O[mf][f][pr * 2 + 0] + pv.x,
                                          O[mf][f][pr * 2 + 1] + pv.y);
    }
}

// ---------------------------------------------------------------------------
extern "C" void kernel_launch(void* const* d_in, const int* in_sizes, int n_in,
                              void* d_out, int out_size)
{
    const float* f1 = (const float*)d_in[0];
    const float* f2 = (const float*)d_in[1];
    const float* f3 = (const float*)d_in[2];
    const float* w1 = (const float*)d_in[3];
    const float* b1 = (const float*)d_in[4];
    const float* w2 = (const float*)d_in[5];
    const float* b2 = (const float*)d_in[6];
    const float* w3 = (const float*)d_in[7];
    const float* b3 = (const float*)d_in[8];
    const float* a1 = (const float*)d_in[9];
    const float* a2 = (const float*)d_in[10];
    const float* a3 = (const float*)d_in[11];
    float* out = (float*)d_out;

    float *p1, *x3, *att2, *att3;
    __half *x1, *x2, *hf1, *hf2, *hf3, *hw1, *hw2, *hw3;
    cudaGetSymbolAddress((void**)&p1,   g_p1);
    cudaGetSymbolAddress((void**)&x3,   g_x3);
    cudaGetSymbolAddress((void**)&att2, g_att2);
    cudaGetSymbolAddress((void**)&att3, g_att3);
    cudaGetSymbolAddress((void**)&x1,   g_x1);
    cudaGetSymbolAddress((void**)&x2,   g_x2);
    cudaGetSymbolAddress((void**)&hf1,  g_f1);
    cudaGetSymbolAddress((void**)&hf2,  g_f2);
    cudaGetSymbolAddress((void**)&hf3,  g_f3);
    cudaGetSymbolAddress((void**)&hw1,  g_w1);
    cudaGetSymbolAddress((void**)&hw2,  g_w2);
    cudaGetSymbolAddress((void**)&hw3,  g_w3);

    cvt_all_kernel<<<7872, 256>>>(f1, f2, f3, w1, w2, w3, b3,
                                  hf1, hf2, hf3, hw1, hw2, hw3, x3);

    const int smemP = (64 * 72 + 64 * 264) * 2;
    cudaFuncSetAttribute(projall_kernel,
                         cudaFuncAttributeMaxDynamicSharedMemorySize, smemP);
    projall_kernel<<<384, 256, smemP>>>(hf1, hw1, b1, p1, x1,
                                        hf2, hw2, b2, x2,
                                        hf3, hw3, x3);

    const int smemG = 2 * 128 * 72 * 2;
    cudaFuncSetAttribute(gram_att3_kernel,
                         cudaFuncAttributeMaxDynamicSharedMemorySize, smemG);
    gram_att3_kernel<<<80, 256, smemG>>>(x2, att2, x3, att3);

    const int smemF = (128 * KST * 2 + 128 * SST) * 2
                      + (33 * 257 + 9 * 65) * 4;
    cudaFuncSetAttribute(fused_mma_kernel,
                         cudaFuncAttributeMaxDynamicSharedMemorySize, smemF);
    fused_mma_kernel<<<dim3(8, BATCH), 512, smemF>>>(
        x1, p1, att2, att3, a1, a2, a3, out);
}